// round 12
// baseline (speedup 1.0000x reference)
#include <cuda_runtime.h>
#include <math.h>

#define S 8192
#define D 2048
#define WSTRIDE 4096           // W row stride (2*D)
#define NCTA_REC 128
#define ROWS_PER_CTA 16        // D / NCTA_REC
#define NCHUNK 64
#define CHUNK 128              // S / NCHUNK
#define REC_THREADS 512
#define RING 32                // hc/cp smem ring slots (power of 2)
#define LEAD 24                // prefetch lead distance (< RING)

typedef unsigned long long ull;

// ---- scratch (no runtime allocation allowed) ----
__device__ float g_hc[(size_t)S * D];        // cummax result
__device__ float g_cp[(size_t)S * D];        // ctx_proj result
__device__ float g_chunkmax[NCHUNK * D];     // per-chunk column maxes
__device__ int   g_flagv[NCTA_REC];          // per-CTA monotonic step counters

#define NEG_INF __int_as_float(0xff800000)

// ---- packed f32x2 helpers ----
__device__ __forceinline__ ull ffma2(ull a, ull b, ull c) {
    ull d;
    asm("fma.rn.f32x2 %0, %1, %2, %3;" : "=l"(d) : "l"(a), "l"(b), "l"(c));
    return d;
}
__device__ __forceinline__ ull pack2(unsigned int lo, unsigned int hi) {
    ull v;
    asm("mov.b64 %0, {%1, %2};" : "=l"(v) : "r"(lo), "r"(hi));
    return v;
}
__device__ __forceinline__ ull pack2f(float x, float y) {
    ull v;
    asm("mov.b64 %0, {%1, %2};" : "=l"(v) : "f"(x), "f"(y));
    return v;
}
__device__ __forceinline__ ull dup2f(float x) {
    ull v;
    asm("mov.b64 %0, {%1, %1};" : "=l"(v) : "f"(x));
    return v;
}
__device__ __forceinline__ float2 unpack2(ull v) {
    float2 r;
    asm("mov.b64 {%0, %1}, %2;" : "=f"(r.x), "=f"(r.y) : "l"(v));
    return r;
}

// ---- fence-free acquire/release primitives (NO atomics) ----
__device__ __forceinline__ int ld_acquire_gpu(const int* p) {
    int v;
    asm volatile("ld.acquire.gpu.global.s32 %0, [%1];" : "=r"(v) : "l"(p) : "memory");
    return v;
}
__device__ __forceinline__ void st_release_gpu(int* p, int v) {
    asm volatile("st.release.gpu.global.s32 [%0], %1;" :: "l"(p), "r"(v) : "memory");
}

// ============================================================
// K1: cummax phase A (per-chunk column max) + flag reset.
// ============================================================
__global__ void cummax_chunk_kernel(const float* __restrict__ ce) {
    int tid = threadIdx.x;
    if (blockIdx.x == 0 && blockIdx.y == 0 && tid < NCTA_REC)
        g_flagv[tid] = 0;
    int col = blockIdx.x * blockDim.x + tid;
    int chunk = blockIdx.y;
    const float* p = ce + (size_t)chunk * CHUNK * D + col;
    float m = NEG_INF;
#pragma unroll 8
    for (int r = 0; r < CHUNK; r++) {
        m = fmaxf(m, p[(size_t)r * D]);
    }
    g_chunkmax[chunk * D + col] = m;
}

// ============================================================
// K2: cummax finish — rebuild exclusive chunk prefix (L2-hot),
// then inclusive-scan own chunk into g_hc.
// ============================================================
__global__ void cummax_finish_kernel(const float* __restrict__ ce) {
    int col = blockIdx.x * blockDim.x + threadIdx.x;
    int chunk = blockIdx.y;
    float m = NEG_INF;
#pragma unroll 8
    for (int ch = 0; ch < chunk; ch++)
        m = fmaxf(m, g_chunkmax[ch * D + col]);
    const float* p = ce + (size_t)chunk * CHUNK * D + col;
    float*       q = g_hc + (size_t)chunk * CHUNK * D + col;
#pragma unroll 8
    for (int r = 0; r < CHUNK; r++) {
        m = fmaxf(m, p[(size_t)r * D]);
        q[(size_t)r * D] = m;
    }
}

// ============================================================
// K3: GEMM: g_cp[t][i] = sum_j ce[t][j] * W[i][D + j] + b[i]
// f32x2 packed FFMA.
// ============================================================
#define GT 128
#define GI 128
#define GK 8
#define GPAD 4

__global__ __launch_bounds__(256) void gemm_ctx_kernel(
    const float* __restrict__ A,
    const float* __restrict__ W,
    const float* __restrict__ bias)
{
    __shared__ float As[GK][GT + GPAD];
    __shared__ float Bs[GK][GI + GPAD];

    int tid = threadIdx.x;
    int tx = tid & 15;
    int ty = tid >> 4;
    int i0 = blockIdx.x * GI;
    int t0 = blockIdx.y * GT;

    int lr = tid >> 1;
    int lk = (tid & 1) * 4;

    const float* Ap = A + (size_t)(t0 + lr) * D + lk;
    const float* Bp = W + (size_t)(i0 + lr) * WSTRIDE + D + lk;

    ull acc[8][4];
#pragma unroll
    for (int m = 0; m < 8; m++)
#pragma unroll
        for (int n = 0; n < 4; n++) acc[m][n] = 0ULL;

    float4 ra = *(const float4*)Ap;
    float4 rb = *(const float4*)Bp;

    for (int kk = 0; kk < D; kk += GK) {
        As[lk + 0][lr] = ra.x; As[lk + 1][lr] = ra.y;
        As[lk + 2][lr] = ra.z; As[lk + 3][lr] = ra.w;
        Bs[lk + 0][lr] = rb.x; Bs[lk + 1][lr] = rb.y;
        Bs[lk + 2][lr] = rb.z; Bs[lk + 3][lr] = rb.w;
        __syncthreads();

        if (kk + GK < D) {
            ra = *(const float4*)(Ap + kk + GK);
            rb = *(const float4*)(Bp + kk + GK);
        }

#pragma unroll
        for (int k = 0; k < GK; k++) {
            float4 a0 = *(const float4*)&As[k][ty * 8];
            float4 a1 = *(const float4*)&As[k][ty * 8 + 4];
            float4 b0 = *(const float4*)&Bs[k][tx * 8];
            float4 b1 = *(const float4*)&Bs[k][tx * 8 + 4];
            ull bp[4] = {pack2f(b0.x, b0.y), pack2f(b0.z, b0.w),
                         pack2f(b1.x, b1.y), pack2f(b1.z, b1.w)};
            ull ad[8] = {dup2f(a0.x), dup2f(a0.y), dup2f(a0.z), dup2f(a0.w),
                         dup2f(a1.x), dup2f(a1.y), dup2f(a1.z), dup2f(a1.w)};
#pragma unroll
            for (int m = 0; m < 8; m++)
#pragma unroll
                for (int n = 0; n < 4; n++)
                    acc[m][n] = ffma2(ad[m], bp[n], acc[m][n]);
        }
        __syncthreads();
    }

    float bv[8];
#pragma unroll
    for (int n = 0; n < 8; n++) bv[n] = bias[i0 + tx * 8 + n];

#pragma unroll
    for (int m = 0; m < 8; m++) {
        size_t row = (size_t)(t0 + ty * 8 + m) * D + i0 + tx * 8;
        float2 c0 = unpack2(acc[m][0]), c1 = unpack2(acc[m][1]);
        float2 c2 = unpack2(acc[m][2]), c3 = unpack2(acc[m][3]);
        float4 o0 = make_float4(c0.x + bv[0], c0.y + bv[1],
                                c1.x + bv[2], c1.y + bv[3]);
        float4 o1 = make_float4(c2.x + bv[4], c2.y + bv[5],
                                c3.x + bv[6], c3.y + bv[7]);
        *(float4*)&g_cp[row]     = o0;
        *(float4*)&g_cp[row + 4] = o1;
    }
}

// ============================================================
// K4: Recurrence v10 = v6 sync (verbatim, best measured) +
// smem hc/cp ring prefetched LEAD steps ahead by warp 8.
// 128 CTAs x 512 threads. c = tid & 127 owns 16 state cols,
// rgrp = tid >> 7 owns 4 rows. W slice in regs (f32x2).
// Wait: warp 0 polls all 128 flags (4 chained acquires/lane).
// Publish: one st.release.gpu per CTA to its own flag.
// hc/cp: warp 8 stages step t+LEAD into s_hc/s_cp each step, so
// finalize reads smem — DRAM latency is off the critical path and
// cannot make this CTA the chip-wide straggler.
// ============================================================
__global__ __launch_bounds__(REC_THREADS, 1) void recurrence_kernel(
    const float* __restrict__ W,
    float* out)
{
    __shared__ float s_red[2][16 * 4];     // [buf][row*4 + colpart]
    __shared__ float s_hc[RING][16];
    __shared__ float s_cp[RING][16];

    int tid  = threadIdx.x;
    int lane = tid & 31;
    int wrp  = tid >> 5;          // 0..15
    int c    = tid & 127;         // column segment
    int rgrp = tid >> 7;          // 0..3
    int wq   = wrp & 3;           // colpart within reduction
    int cta  = blockIdx.x;
    int i0   = cta * ROWS_PER_CTA;

    // ---- preload W slice as f32x2 pairs ----
    ull w2[4][8];
#pragma unroll
    for (int m = 0; m < 4; m++) {
        const float* wp = W + (size_t)(i0 + rgrp * 4 + m) * WSTRIDE + c * 16;
#pragma unroll
        for (int j = 0; j < 4; j++) {
            uint4 q = *(const uint4*)(wp + j * 4);
            w2[m][j * 2 + 0] = pack2(q.x, q.y);
            w2[m][j * 2 + 1] = pack2(q.z, q.w);
        }
    }

    // ---- prologue: fill ring slots 0..LEAD-1 (warps 8-15 split) ----
    if (wrp >= 8) {
        for (int p = wrp - 8; p < LEAD; p += 8) {
            if (lane < 16)
                s_hc[p][lane] = __ldg(&g_hc[(size_t)p * D + i0 + lane]);
            else
                s_cp[p][lane - 16] = __ldg(&g_cp[(size_t)p * D + i0 + lane - 16]);
        }
    }

    const ull minus1 = pack2(__float_as_uint(-1.0f), __float_as_uint(-1.0f));

    for (int t = 0; t < S; t++) {
        // ---- wait until ALL 128 CTAs have published row t-1 (v6) ----
        if (t > 0 && wrp == 0) {
            const int* fp = g_flagv + lane;
            for (;;) {
                int f0 = ld_acquire_gpu(fp);
                int f1 = ld_acquire_gpu(fp + 32);
                int f2 = ld_acquire_gpu(fp + 64);
                int f3 = ld_acquire_gpu(fp + 96);
                int mn = min(min(f0, f1), min(f2, f3));
                if (__all_sync(0xFFFFFFFFu, mn >= t)) break;
            }
        }
        __syncthreads();   // join pollers + propagate acquire ordering
                           // (also covers prologue ring fill at t==0)

        // ---- warp 8: stage hc/cp for step t+LEAD into the ring ----
        // slot (t+LEAD)&31 was last read at step t+LEAD-RING (= t-8),
        // separated from this write by many __syncthreads -> safe.
        if (wrp == 8 && t + LEAD < S) {
            int slot = (t + LEAD) & (RING - 1);
            if (lane < 16)
                s_hc[slot][lane] = __ldg(&g_hc[(size_t)(t + LEAD) * D + i0 + lane]);
            else
                s_cp[slot][lane - 16] = __ldg(&g_cp[(size_t)(t + LEAD) * D + i0 + lane - 16]);
        }

        // ---- obtain state segment (plain cached loads) ----
        ull sp[8];
        if (t == 0) {
#pragma unroll
            for (int j = 0; j < 8; j++) sp[j] = minus1;
        } else {
            const float* src = out + (size_t)(t - 1) * D + c * 16;
#pragma unroll
            for (int j = 0; j < 4; j++) {
                uint4 q = *(const uint4*)(src + j * 4);
                sp[j * 2 + 0] = pack2(q.x, q.y);
                sp[j * 2 + 1] = pack2(q.z, q.w);
            }
        }

        // ---- 4-row x 16-col partial matvec, packed f32x2 ----
        ull a0 = 0, a1 = 0, a2 = 0, a3 = 0;
#pragma unroll
        for (int j = 0; j < 8; j++) {
            a0 = ffma2(w2[0][j], sp[j], a0);
            a1 = ffma2(w2[1][j], sp[j], a1);
            a2 = ffma2(w2[2][j], sp[j], a2);
            a3 = ffma2(w2[3][j], sp[j], a3);
        }
        float2 f0 = unpack2(a0), f1 = unpack2(a1),
               f2 = unpack2(a2), f3 = unpack2(a3);
        float r0 = f0.x + f0.y;
        float r1 = f1.x + f1.y;
        float r2 = f2.x + f2.y;
        float r3 = f3.x + f3.y;

        // ---- warp shuffle reduction over 32 column segments ----
#pragma unroll
        for (int off = 16; off > 0; off >>= 1) {
            r0 += __shfl_xor_sync(0xFFFFFFFFu, r0, off);
            r1 += __shfl_xor_sync(0xFFFFFFFFu, r1, off);
            r2 += __shfl_xor_sync(0xFFFFFFFFu, r2, off);
            r3 += __shfl_xor_sync(0xFFFFFFFFu, r3, off);
        }
        int buf = t & 1;
        if (lane == 0) {
            int rb = rgrp * 4;
            s_red[buf][(rb + 0) * 4 + wq] = r0;
            s_red[buf][(rb + 1) * 4 + wq] = r1;
            s_red[buf][(rb + 2) * 4 + wq] = r2;
            s_red[buf][(rb + 3) * 4 + wq] = r3;
        }
        __syncthreads();

        // ---- finalize: 16 lanes of warp 0; hc/cp from the smem ring ----
        if (tid < ROWS_PER_CTA) {
            int slot = t & (RING - 1);
            float hcv = s_hc[slot][tid];
            float cpv = s_cp[slot][tid];
            float4 v = *(const float4*)&s_red[buf][tid * 4];
            float s = (v.x + v.y) + (v.z + v.w);
            float x  = s + cpv;
            float g  = 1.0f / (1.0f + __expf(-x));
            float ns = hcv * g;
            __stcg(&out[(size_t)t * D + i0 + tid], ns);
            if (t == S - 1) __stcg(&out[(size_t)S * D + i0 + tid], ns);
            __syncwarp(0x0000FFFFu);   // all 16 row stores done
            if (tid == 0)
                st_release_gpu(&g_flagv[cta], t + 1);   // publish step t
        }
        // s_red reuse at t+1 is safe: writes at t+1 occur after the t+1
        // top-of-loop __syncthreads, which follows every reader's access.
        // Ring slot (t+LEAD)&31 write vs its read at t+LEAD: separated by
        // LEAD top-of-loop barriers.
    }
}

// ============================================================
extern "C" void kernel_launch(void* const* d_in, const int* in_sizes, int n_in,
                              void* d_out, int out_size) {
    const float* ce = (const float*)d_in[0];   // (S, D)
    const float* W  = (const float*)d_in[1];   // (D, 2D)
    const float* b  = (const float*)d_in[2];   // (D,)
    float* out = (float*)d_out;                // (S*D + D) floats

    dim3 cgrid(D / 256, NCHUNK);
    cummax_chunk_kernel<<<cgrid, 256>>>(ce);    // launch 1 (+ flag reset)
    cummax_finish_kernel<<<cgrid, 256>>>(ce);   // launch 2

    dim3 ggrid(D / GI, S / GT);
    gemm_ctx_kernel<<<ggrid, 256>>>(ce, W, b);  // launch 3

    recurrence_kernel<<<NCTA_REC, REC_THREADS>>>(W, out);  // launch 4
}